// round 15
// baseline (speedup 1.0000x reference)
#include <cuda_runtime.h>
#include <cuda_fp16.h>
#include <cstdint>
#include <math.h>

// Problem constants
#define V_   32000
#define C_   768
#define T_   1024
#define H_   12
#define HS_  64
#define FF_  9216
#define NB_  3
#define B_   4
#define M_   (B_ * T_)
#define EPS_ 1e-5f
#define SCALE_ 0.03608439182435161f   // 768^-0.5
#define NCB_  (V_ / 128)

// FP16 GEMM tiling: CTA 128x128x64, 8 warps of 64x32, 2-stage cp.async.
// A [M,K] and B [N,K] both K-major, stride 72 halves (144B rows, plain-LDSM
// conflict-free). No trans-ldmatrix anywhere.
#define AH_STR 72
#define AH_SZ  (128 * AH_STR)           // per stage (A: 128 rows)
#define BHN_SZ (128 * AH_STR)           // per stage (B: 128 n-rows)
#define GH_SMEM (2 * (AH_SZ + BHN_SZ) * 2)     // 73728 bytes

// BM=64 variant (proj / FF2)
#define AH64_SZ (64 * AH_STR)
#define GH64_SMEM (2 * (AH64_SZ + BHN_SZ) * 2) // 55296 bytes

// Attention: fp16 tiles, stride 72 halves; Q tile = 128 rows, KV tile = 64
#define AST 72

// Epilogue modes
#define MODE_PLAIN 0
#define MODE_ADD   1
#define MODE_HALF  2
#define MODE_RELU  3

// ----------------------------------------------------------------------------
// Scratch  (all weight buffers now hold [N, K] layouts)
// ----------------------------------------------------------------------------
__device__ float  g_x[M_ * C_];
__device__ __half g_h[M_ * C_];
__device__ __half g_qkv[M_ * 3 * C_];
__device__ __half g_o[M_ * C_];
__device__ __half g_wqkv[NB_ * 3 * C_ * C_];        // [blk][N=2304][K=768]
__device__ __half g_wproj[NB_ * C_ * C_];           // [blk][N=768][K=768]
__device__ __half g_wf1[(size_t)NB_ * FF_ * C_];    // [blk][N=9216][K=768]
__device__ __half g_wf2[(size_t)NB_ * C_ * FF_];    // [blk][N=768][K=9216]
__device__ __half g_wlm[(size_t)V_ * C_];           // [N=32000][K=768]
__device__ __half g_ff[(size_t)M_ * FF_];
__device__ float  g_pm[(size_t)M_ * NCB_];
__device__ float  g_ps[(size_t)M_ * NCB_];
__device__ float  g_rowloss[M_];

// ----------------------------------------------------------------------------
// PTX helpers
// ----------------------------------------------------------------------------
#define CP16(dst, src) asm volatile("cp.async.cg.shared.global [%0], [%1], 16;\n" :: "r"(dst), "l"(src) : "memory")
#define CP_COMMIT() asm volatile("cp.async.commit_group;\n" ::: "memory")

__device__ __forceinline__ void mma_f16(float* c, const uint32_t* a, uint32_t b0, uint32_t b1) {
    asm volatile("mma.sync.aligned.m16n8k16.row.col.f32.f16.f16.f32 "
                 "{%0,%1,%2,%3}, {%4,%5,%6,%7}, {%8,%9}, {%0,%1,%2,%3};"
                 : "+f"(c[0]), "+f"(c[1]), "+f"(c[2]), "+f"(c[3])
                 : "r"(a[0]), "r"(a[1]), "r"(a[2]), "r"(a[3]), "r"(b0), "r"(b1));
}

#define LDSM_X4(r, addr) \
    asm volatile("ldmatrix.sync.aligned.m8n8.x4.shared.b16 {%0,%1,%2,%3}, [%4];" \
                 : "=r"((r)[0]), "=r"((r)[1]), "=r"((r)[2]), "=r"((r)[3]) : "r"(addr))
#define LDSM_X4_T(r, addr) \
    asm volatile("ldmatrix.sync.aligned.m8n8.x4.trans.shared.b16 {%0,%1,%2,%3}, [%4];" \
                 : "=r"((r)[0]), "=r"((r)[1]), "=r"((r)[2]), "=r"((r)[3]) : "r"(addr))

__device__ __forceinline__ void sm_merge(float& m, float& s, float m2, float s2) {
    float mm = fmaxf(m, m2);
    s = s * __expf(m - mm) + s2 * __expf(m2 - mm);
    m = mm;
}

// ----------------------------------------------------------------------------
// Weight transpose + fp32->fp16: in [R][Cc] -> out [Cc][R]  (smem tiled)
// ----------------------------------------------------------------------------
__global__ void transp_h(const float* __restrict__ in, __half* __restrict__ out,
                         int R, int Cc) {
    __shared__ float t[32][33];
    int c0 = blockIdx.x * 32, r0 = blockIdx.y * 32;
    int tx = threadIdx.x, ty = threadIdx.y;          // 32 x 8
#pragma unroll
    for (int i = 0; i < 32; i += 8)
        t[ty + i][tx] = in[(size_t)(r0 + ty + i) * Cc + c0 + tx];
    __syncthreads();
#pragma unroll
    for (int i = 0; i < 32; i += 8)
        out[(size_t)(c0 + ty + i) * R + r0 + tx] = __float2half_rn(t[tx][ty + i]);
}

// ----------------------------------------------------------------------------
// Pack wq/wk/wv for all blocks into [blk][N=2304][K=768] fp16 (smem tiled)
// grid (2304/32, 768/32, NB), block (32, 8)
// ----------------------------------------------------------------------------
__global__ void pack_qkv_all(const float* __restrict__ wq, const float* __restrict__ wk,
                             const float* __restrict__ wv) {
    __shared__ float t[32][33];
    int n0 = blockIdx.x * 32, c0 = blockIdx.y * 32, blk = blockIdx.z;
    int tx = threadIdx.x, ty = threadIdx.y;
    int part = n0 / C_;
    int j0 = n0 - part * C_;
    const float* w = (part == 0) ? wq : (part == 1 ? wk : wv);
    w += (size_t)blk * H_ * C_ * HS_;
    int h = j0 / HS_, d0 = j0 & (HS_ - 1);           // constant across tile
#pragma unroll
    for (int i = 0; i < 32; i += 8)
        t[ty + i][tx] = w[((size_t)h * C_ + c0 + ty + i) * HS_ + d0 + tx];
    __syncthreads();
    __half* dst = g_wqkv + (size_t)blk * 3 * C_ * C_;
#pragma unroll
    for (int i = 0; i < 32; i += 8)
        dst[(size_t)(n0 + ty + i) * C_ + c0 + tx] = __float2half_rn(t[tx][ty + i]);
}

// ----------------------------------------------------------------------------
// Embedding
// ----------------------------------------------------------------------------
__global__ void embed_k(const float4* __restrict__ tok, const float4* __restrict__ pos,
                        const int* __restrict__ src) {
    int idx = blockIdx.x * blockDim.x + threadIdx.x;
    int row = idx / 192;
    int c4  = idx - row * 192;
    int t   = row % T_;
    float4 a = tok[(size_t)src[row] * 192 + c4];
    float4 p = pos[t * 192 + c4];
    ((float4*)g_x)[idx] = make_float4(a.x + p.x, a.y + p.y, a.z + p.z, a.w + p.w);
}

// ----------------------------------------------------------------------------
// LayerNorm: warp per row, fp16 out
// ----------------------------------------------------------------------------
__global__ void __launch_bounds__(256) ln_k(const float* __restrict__ in, __half* __restrict__ out,
                                            const float* __restrict__ g, const float* __restrict__ b) {
    int warp = threadIdx.x >> 5, lane = threadIdx.x & 31;
    int row = blockIdx.x * 8 + warp;
    const float4* x4 = (const float4*)(in + (size_t)row * C_);

    float4 v[6];
    float s = 0.f, s2 = 0.f;
#pragma unroll
    for (int i = 0; i < 6; i++) {
        v[i] = x4[lane + 32 * i];
        s  += v[i].x + v[i].y + v[i].z + v[i].w;
        s2 += v[i].x * v[i].x + v[i].y * v[i].y + v[i].z * v[i].z + v[i].w * v[i].w;
    }
#pragma unroll
    for (int o = 16; o > 0; o >>= 1) {
        s  += __shfl_xor_sync(0xffffffffu, s, o);
        s2 += __shfl_xor_sync(0xffffffffu, s2, o);
    }
    float mean = s * (1.f / C_);
    float var  = s2 * (1.f / C_) - mean * mean;
    float inv  = rsqrtf(var + EPS_);

    const float4* g4 = (const float4*)g;
    const float4* b4 = (const float4*)b;
    uint2* o4 = (uint2*)(out + (size_t)row * C_);
#pragma unroll
    for (int i = 0; i < 6; i++) {
        float4 gg = g4[lane + 32 * i], bb = b4[lane + 32 * i];
        __half2 h0 = __floats2half2_rn((v[i].x - mean) * inv * gg.x + bb.x,
                                       (v[i].y - mean) * inv * gg.y + bb.y);
        __half2 h1 = __floats2half2_rn((v[i].z - mean) * inv * gg.z + bb.z,
                                       (v[i].w - mean) * inv * gg.w + bb.w);
        o4[lane + 32 * i] = make_uint2(*(uint32_t*)&h0, *(uint32_t*)&h1);
    }
}

// ----------------------------------------------------------------------------
// FP16 GEMM (BM=128): C[M,N] = A[M,K] @ B[N,K]^T, BK=64, 2-stage cp.async.
// Both operands plain-LDSM from stride-72 K-major smem tiles.
// ----------------------------------------------------------------------------
__device__ __forceinline__ void gh_load(uint32_t sa, uint32_t sb,
                                        const __half* Ag, const __half* Bg,
                                        int K, int tid) {
#pragma unroll
    for (int i = 0; i < 4; i++) {
        int idx = tid + i * 256;
        int row = idx >> 3, q = idx & 7;
        CP16(sa + (uint32_t)((row * AH_STR + q * 8) * 2), Ag + (size_t)row * K + q * 8);
    }
#pragma unroll
    for (int i = 0; i < 4; i++) {
        int idx = tid + i * 256;
        int row = idx >> 3, q = idx & 7;
        CP16(sb + (uint32_t)((row * AH_STR + q * 8) * 2), Bg + (size_t)row * K + q * 8);
    }
    CP_COMMIT();
}

template<int MODE>
__global__ void __launch_bounds__(256)
gemm_h(const __half* __restrict__ A, const __half* __restrict__ B,
       void* __restrict__ Cv, const float* __restrict__ bias,
       int K, int N) {
    extern __shared__ __half hs[];
    uint32_t s_u = (uint32_t)__cvta_generic_to_shared(hs);
    uint32_t a_b[2] = { s_u, s_u + (uint32_t)((AH_SZ + BHN_SZ) * 2) };
    uint32_t b_b[2] = { a_b[0] + AH_SZ * 2, a_b[1] + AH_SZ * 2 };

    int tid  = threadIdx.x;
    int warp = tid >> 5, lane = tid & 31;
    int brow = blockIdx.x * 128;
    int bcol = blockIdx.y * 128;
    int wm = (warp & 1) * 64, wn = (warp >> 1) * 32;
    int gid = lane >> 2, tg = lane & 3;
    int l16 = lane & 15, lh = lane >> 4;

    float acc[4][4][4];
#pragma unroll
    for (int i = 0; i < 4; i++)
#pragma unroll
        for (int j = 0; j < 4; j++)
#pragma unroll
            for (int r = 0; r < 4; r++) acc[i][j][r] = 0.f;

    const __half* Abase = A + (size_t)brow * K;
    const __half* Bbase = B + (size_t)bcol * K;

    int nk = K / 64;
    gh_load(a_b[0], b_b[0], Abase, Bbase, K, tid);

    for (int kt = 0; kt < nk; kt++) {
        int s = kt & 1;
        if (kt + 1 < nk) {
            gh_load(a_b[s ^ 1], b_b[s ^ 1], Abase + (kt + 1) * 64,
                    Bbase + (kt + 1) * 64, K, tid);
            asm volatile("cp.async.wait_group 1;\n" ::: "memory");
        } else {
            asm volatile("cp.async.wait_group 0;\n" ::: "memory");
        }
        __syncthreads();

#pragma unroll
        for (int ks = 0; ks < 4; ks++) {
            uint32_t af[4][4], bfr[2][4];
#pragma unroll
            for (int mt = 0; mt < 4; mt++)
                LDSM_X4(af[mt], a_b[s] + (uint32_t)(((wm + mt * 16 + l16) * AH_STR
                                                    + ks * 16 + lh * 8) * 2));
#pragma unroll
            for (int np = 0; np < 2; np++)
                LDSM_X4(bfr[np], b_b[s] + (uint32_t)(((wn + np * 16 + l16) * AH_STR
                                                     + ks * 16 + lh * 8) * 2));
#pragma unroll
            for (int mt = 0; mt < 4; mt++)
#pragma unroll
                for (int nt = 0; nt < 4; nt++)
                    mma_f16(acc[mt][nt], af[mt], bfr[nt >> 1][nt & 1],
                            bfr[nt >> 1][(nt & 1) + 2]);
        }
        __syncthreads();
    }

    // ---------------- epilogue ----------------
    if (MODE == MODE_HALF || MODE == MODE_RELU || MODE == MODE_ADD) {
#pragma unroll
        for (int mt = 0; mt < 4; mt++) {
            int r0 = brow + wm + mt * 16 + gid;
#pragma unroll
            for (int nt = 0; nt < 4; nt++) {
                int c0 = bcol + wn + nt * 8 + tg * 2;
                float b0v = bias ? bias[c0] : 0.f;
                float b1v = bias ? bias[c0 + 1] : 0.f;
                float v0 = acc[mt][nt][0] + b0v, v1 = acc[mt][nt][1] + b1v;
                float v2 = acc[mt][nt][2] + b0v, v3 = acc[mt][nt][3] + b1v;
                if (MODE == MODE_HALF || MODE == MODE_RELU) {
                    if (MODE == MODE_RELU) {
                        v0 = fmaxf(v0, 0.f); v1 = fmaxf(v1, 0.f);
                        v2 = fmaxf(v2, 0.f); v3 = fmaxf(v3, 0.f);
                    }
                    __half* ph = (__half*)Cv;
                    *(__half2*)(ph + (size_t)r0 * N + c0)       = __floats2half2_rn(v0, v1);
                    *(__half2*)(ph + (size_t)(r0 + 8) * N + c0) = __floats2half2_rn(v2, v3);
                } else {
                    float* pf = (float*)Cv;
                    float* p0 = pf + (size_t)r0 * N + c0;
                    float* p1 = pf + (size_t)(r0 + 8) * N + c0;
                    v0 += p0[0]; v1 += p0[1]; v2 += p1[0]; v3 += p1[1];
                    p0[0] = v0; p0[1] = v1; p1[0] = v2; p1[1] = v3;
                }
            }
        }
    } else {
        // MODE_PLAIN: store logits + per-row online-softmax partials
        float bb0[4], bb1[4];
#pragma unroll
        for (int nt = 0; nt < 4; nt++) {
            int c0 = bcol + wn + nt * 8 + tg * 2;
            bb0[nt] = bias ? bias[c0] : 0.f;
            bb1[nt] = bias ? bias[c0 + 1] : 0.f;
        }
        float rm[4][2], rs[4][2];
#pragma unroll
        for (int mt = 0; mt < 4; mt++) { rm[mt][0] = rm[mt][1] = -3.4e38f; rs[mt][0] = rs[mt][1] = 0.f; }

        float* pf = (float*)Cv;
#pragma unroll
        for (int mt = 0; mt < 4; mt++) {
            int r0 = brow + wm + mt * 16 + gid;
#pragma unroll
            for (int nt = 0; nt < 4; nt++) {
                int c0 = bcol + wn + nt * 8 + tg * 2;
                float v0 = acc[mt][nt][0] + bb0[nt], v1 = acc[mt][nt][1] + bb1[nt];
                float v2 = acc[mt][nt][2] + bb0[nt], v3 = acc[mt][nt][3] + bb1[nt];
                pf[(size_t)r0 * N + c0]           = v0;
                pf[(size_t)r0 * N + c0 + 1]       = v1;
                pf[(size_t)(r0 + 8) * N + c0]     = v2;
                pf[(size_t)(r0 + 8) * N + c0 + 1] = v3;
                rm[mt][0] = fmaxf(rm[mt][0], fmaxf(v0, v1));
                rm[mt][1] = fmaxf(rm[mt][1], fmaxf(v2, v3));
            }
        }
#pragma unroll
        for (int mt = 0; mt < 4; mt++)
#pragma unroll
            for (int nt = 0; nt < 4; nt++) {
                rs[mt][0] += __expf(acc[mt][nt][0] + bb0[nt] - rm[mt][0])
                           + __expf(acc[mt][nt][1] + bb1[nt] - rm[mt][0]);
                rs[mt][1] += __expf(acc[mt][nt][2] + bb0[nt] - rm[mt][1])
                           + __expf(acc[mt][nt][3] + bb1[nt] - rm[mt][1]);
            }
#pragma unroll
        for (int mt = 0; mt < 4; mt++)
#pragma unroll
            for (int hf = 0; hf < 2; hf++) {
#pragma unroll
                for (int o = 1; o <= 2; o <<= 1) {
                    float m2 = __shfl_xor_sync(0xffffffffu, rm[mt][hf], o);
                    float s2 = __shfl_xor_sync(0xffffffffu, rs[mt][hf], o);
                    sm_merge(rm[mt][hf], rs[mt][hf], m2, s2);
                }
            }
        __syncthreads();
        float* fs = (float*)hs;
        int wg = warp >> 1;
        if (tg == 0) {
#pragma unroll
            for (int mt = 0; mt < 4; mt++)
#pragma unroll
                for (int hf = 0; hf < 2; hf++) {
                    int rl = wm + mt * 16 + gid + hf * 8;
                    fs[rl * 4 + wg]       = rm[mt][hf];
                    fs[512 + rl * 4 + wg] = rs[mt][hf];
                }
        }
        __syncthreads();
        if (tid < 128) {
            float m = fs[tid * 4], s = fs[512 + tid * 4];
            sm_merge(m, s, fs[tid * 4 + 1], fs[512 + tid * 4 + 1]);
            sm_merge(m, s, fs[tid * 4 + 2], fs[512 + tid * 4 + 2]);
            sm_merge(m, s, fs[tid * 4 + 3], fs[512 + tid * 4 + 3]);
            size_t off = (size_t)(brow + tid) * gridDim.y + blockIdx.y;
            g_pm[off] = m;
            g_ps[off] = s;
        }
    }
}

// ----------------------------------------------------------------------------
// FP16 GEMM (BM=64, MODE_ADD): proj / FF2. B is [N,K].
// ----------------------------------------------------------------------------
__device__ __forceinline__ void gh_load64(uint32_t sa, uint32_t sb,
                                          const __half* Ag, const __half* Bg,
                                          int K, int tid) {
#pragma unroll
    for (int i = 0; i < 2; i++) {
        int idx = tid + i * 256;
        int row = idx >> 3, q = idx & 7;
        CP16(sa + (uint32_t)((row * AH_STR + q * 8) * 2), Ag + (size_t)row * K + q * 8);
    }
#pragma unroll
    for (int i = 0; i < 4; i++) {
        int idx = tid + i * 256;
        int row = idx >> 3, q = idx & 7;
        CP16(sb + (uint32_t)((row * AH_STR + q * 8) * 2), Bg + (size_t)row * K + q * 8);
    }
    CP_COMMIT();
}

__global__ void __launch_bounds__(256)
gemm_h64_add(const __half* __restrict__ A, const __half* __restrict__ B,
             float* __restrict__ Cf, const float* __restrict__ bias,
             int K, int N) {
    extern __shared__ __half hs[];
    uint32_t s_u = (uint32_t)__cvta_generic_to_shared(hs);
    uint32_t a_b[2] = { s_u, s_u + (uint32_t)((AH64_SZ + BHN_SZ) * 2) };
    uint32_t b_b[2] = { a_b[0] + AH64_SZ * 2, a_b[1] + AH64_SZ * 2 };

    int tid  = threadIdx.x;
    int warp = tid >> 5, lane = tid & 31;
    int brow = blockIdx.x * 64;
    int bcol = blockIdx.y * 128;
    int wm = (warp & 1) * 32, wn = (warp >> 1) * 32;
    int gid = lane >> 2, tg = lane & 3;
    int l16 = lane & 15, lh = lane >> 4;

    float acc[2][4][4];
#pragma unroll
    for (int i = 0; i < 2; i++)
#pragma unroll
        for (int j = 0; j < 4; j++)
#pragma unroll
            for (int r = 0; r < 4; r++) acc[i][j][r] = 0.f;

    const __half* Abase = A + (size_t)brow * K;
    const __half* Bbase = B + (size_t)bcol * K;

    int nk = K / 64;
    gh_load64(a_b[0], b_b[0], Abase, Bbase, K, tid);

    for (int kt = 0; kt < nk; kt++) {
        int s = kt & 1;
        if (kt + 1 < nk) {
            gh_load64(a_b[s ^ 1], b_b[s ^ 1], Abase + (kt + 1) * 64,
                      Bbase + (kt + 1) * 64, K, tid);
            asm volatile("cp.async.wait_group 1;\n" ::: "memory");
        } else {
            asm volatile("cp.async.wait_group 0;\n" ::: "memory");
        }
        __syncthreads();

#pragma unroll
        for (int ks = 0; ks < 4; ks++) {
            uint32_t af[2][4], bfr[2][4];
#pragma unroll
            for (int mt = 0; mt < 2; mt++)
                LDSM_X4(af[mt], a_b[s] + (uint32_t)(((wm + mt * 16 + l16) * AH_STR
                                                    + ks * 16 + lh * 8) * 2));
#pragma unroll
            for (int np = 0; np < 2; np++)
                LDSM_X4(bfr[np], b_b[s] + (uint32_t)(((wn + np * 16 + l16) * AH_STR
                                                     + ks * 16 + lh * 8) * 2));
#pragma unroll
            for (int mt = 0; mt < 2; mt++)
#pragma unroll
                for (int nt = 0; nt < 4; nt++)
                    mma_f16(acc[mt][nt], af[mt], bfr[nt >> 1][nt & 1],
                            bfr[nt >> 1][(nt & 1) + 2]);
        }
        __syncthreads();
    }

#pragma unroll
    for (int mt = 0; mt < 2; mt++) {
        int r0 = brow + wm + mt * 16 + gid;
#pragma unroll
        for (int nt = 0; nt < 4; nt++) {
            int c0 = bcol + wn + nt * 8 + tg * 2;
            float b0v = bias[c0], b1v = bias[c0 + 1];
            float* p0 = Cf + (size_t)r0 * N + c0;
            float* p1 = Cf + (size_t)(r0 + 8) * N + c0;
            p0[0] = acc[mt][nt][0] + b0v + p0[0];
            p0[1] = acc[mt][nt][1] + b1v + p0[1];
            p1[0] = acc[mt][nt][2] + b0v + p1[0];
            p1[1] = acc[mt][nt][3] + b1v + p1[1];
        }
    }
}

// ----------------------------------------------------------------------------
// FP16 flash attention (unchanged from round 14; P in registers)
// ----------------------------------------------------------------------------
__global__ void __launch_bounds__(256) attn_flash() {
    __shared__ __half ahs[(128 + 64 + 64) * AST];
    __half* Qs = ahs;
    __half* Ks = ahs + 128 * AST;
    __half* Vs = ahs + (128 + 64) * AST;
    uint32_t qs_u = (uint32_t)__cvta_generic_to_shared(Qs);
    uint32_t ks_u = qs_u + 128 * AST * 2;
    uint32_t vs_u = qs_u + (128 + 64) * AST * 2;

    int qi = blockIdx.x, h = blockIdx.y, b = blockIdx.z;
    int q0 = qi * 128;
    int tid = threadIdx.x, lane = tid & 31, w = tid >> 5;
    int gid = lane >> 2, tg = lane & 3;
    int l16 = lane & 15, lh = lane >> 4;
    size_t base = (size_t)(b * T_) * (3 * C_);
    int hoff = h * HS_;

    for (int i = tid; i < 128 * 8; i += 256) {
        int r = i >> 3, c8 = (i & 7) << 3;
        *(uint4*)&Qs[r * AST + c8] =
            *(const uint4*)&g_qkv[base + (size_t)(q0 + r) * 3 * C_ + hoff + c8];
    }
    __syncthreads();

    uint32_t qf[4][4];
#pragma unroll
    for (int ks = 0; ks < 4; ks++)
        LDSM_X4(qf[ks], qs_u + (uint32_t)(((w * 16 + l16) * AST + ks * 16 + lh * 8) * 2));

    float m0 = -1e30f, m1 = -1e30f, l0 = 0.f, l1 = 0.f;
    float acc_o[8][4];
#pragma unroll
    for (int nt = 0; nt < 8; nt++)
#pragma unroll
        for (int r = 0; r < 4; r++) acc_o[nt][r] = 0.f;

    int row0 = q0 + w * 16 + gid;
    int row1 = row0 + 8;

    for (int j0 = 0; j0 < q0 + 128; j0 += 64) {
        __syncthreads();
        for (int i = tid; i < 64 * 8; i += 256) {
            int r = i >> 3, c8 = (i & 7) << 3;
            size_t rb = base + (size_t)(j0 + r) * 3 * C_ + hoff + c8;
            *(uint4*)&Ks[r * AST + c8] = *(const uint4*)&g_qkv[rb + C_];
            *(uint4*)&Vs[r * AST + c8] = *(const uint4*)&g_qkv[rb + 2 * C_];
        }
        __syncthreads();

        float sc[8][4];
#pragma unroll
        for (int nt = 0; nt < 8; nt++)
#pragma unroll
            for (int r = 0; r < 4; r++) sc[nt][r] = 0.f;
#pragma unroll
        for (int ks = 0; ks < 4; ks++) {
            uint32_t bk[4][4];
#pragma unroll
            for (int np = 0; np < 4; np++)
                LDSM_X4(bk[np], ks_u + (uint32_t)(((np * 16 + l16) * AST + ks * 16 + lh * 8) * 2));
#pragma unroll
            for (int nt = 0; nt < 8; nt++)
                mma_f16(sc[nt], qf[ks], bk[nt >> 1][nt & 1], bk[nt >> 1][(nt & 1) + 2]);
        }

        bool needmask = (j0 + 63 > row0);
#pragma unroll
        for (int nt = 0; nt < 8; nt++) {
            sc[nt][0] *= SCALE_; sc[nt][1] *= SCALE_;
            sc[nt][2] *= SCALE_; sc[nt][3] *= SCALE_;
            if (needmask) {
                int jg = j0 + nt * 8 + tg * 2;
                if (jg > row0)     sc[nt][0] = -1e30f;
                if (jg + 1 > row0) sc[nt][1] = -1e30f;
                if (jg > row1)     sc[nt][2] = -1e30f;
                if (jg + 1 > row1) sc[nt][3] = -1e30f;
            }
        }

        float mx0 = -1e30f, mx1 = -1e30f;
#pragma unroll
        for (int nt = 0; nt < 8; nt++) {
            mx0 = fmaxf(mx0, fmaxf(sc[nt][0], sc[nt][1]));
            mx1 = fmaxf(mx1, fmaxf(sc[nt][2], sc[nt][3]));
        }
        mx0 = fmaxf(mx0, __shfl_xor_sync(0xffffffffu, mx0, 1));
        mx0 = fmaxf(mx0, __shfl_xor_sync(0xffffffffu, mx0, 2));
        mx1 = fmaxf(mx1, __shfl_xor_sync(0xffffffffu, mx1, 1));
        mx1 = fmaxf(mx1, __shfl_xor_sync(0xffffffffu, mx1, 2));

        float mn0 = fmaxf(m0, mx0), mn1 = fmaxf(m1, mx1);
        float a0 = __expf(m0 - mn0), a1 = __expf(m1 - mn1);
        m0 = mn0; m1 = mn1;

        float s0 = 0.f, s1 = 0.f;
#pragma unroll
        for (int nt = 0; nt < 8; nt++) {
            float p0 = __expf(sc[nt][0] - mn0), p1 = __expf(sc[nt][1] - mn0);
            float p2 = __expf(sc[nt][2] - mn1), p3 = __expf(sc[nt][3] - mn1);
            s0 += p0 + p1; s1 += p2 + p3;
            sc[nt][0] = p0; sc[nt][1] = p1; sc[nt][2] = p2; sc[nt][3] = p3;
        }
        s0 += __shfl_xor_sync(0xffffffffu, s0, 1);
        s0 += __shfl_xor_sync(0xffffffffu, s0, 2);
        s1 += __shfl_xor_sync(0xffffffffu, s1, 1);
        s1 += __shfl_xor_sync(0xffffffffu, s1, 2);
        l0 = l0 * a0 + s0;
        l1 = l1 * a1 + s1;

#pragma unroll
        for (int nt = 0; nt < 8; nt++) {
            acc_o[nt][0] *= a0; acc_o[nt][1] *= a0;
            acc_o[nt][2] *= a1; acc_o[nt][3] *= a1;
        }

#pragma unroll
        for (int ks = 0; ks < 4; ks++) {
            uint32_t pf[4];
            __half2 t0 = __floats2half2_rn(sc[2 * ks][0],     sc[2 * ks][1]);
            __half2 t1 = __floats2half2_rn(sc[2 * ks][2],     sc[2 * ks][3]);
            __half2 t2 = __floats2half2_rn(sc[2 * ks + 1][0], sc[2 * ks + 1][1]);
            __half2 t3 = __floats2half2_rn(sc[2 * ks + 1][2], sc[2 * ks + 1][3]);
            pf[0] = *(uint32_t*)&t0; pf[1] = *(uint32_t*)&t1;
            pf[2] = *(uint32_t*)&t2; pf[3] = *(uint32_t*)&t3;
            uint32_t bv[4][4];
#pragma unroll
            for (int np = 0; np < 4; np++)
                LDSM_X4_T(bv[np], vs_u + (uint32_t)(((ks * 16 + l16) * AST + np * 16 + lh * 8) * 2));
#pragma unroll
            for (int nt = 0; nt < 8; nt++)
                mma_f16(acc_o[nt], pf, bv[nt >> 1][(nt & 1) * 2], bv[nt >> 1][(nt & 1) * 2 + 1]);
        }
    }

    float i0 = 1.f / l0, i1 = 1.f / l1;
#pragma unroll
    for (int nt = 0; nt < 8; nt++) {
        __half2 h0 = __floats2half2_rn(acc_o[nt][0] * i0, acc_o[nt][1] * i0);
        __half2 h1 = __floats2half2_rn(acc_o[nt][2] * i1, acc_o[nt][3] * i1);
        *(__half2*)&g_o[(size_t)(b * T_ + row0) * C_ + hoff + nt * 8 + 2 * tg] = h0;
        *(__half2*)&g_o[(size_t)(b * T_ + row1) * C_ + hoff + nt * 8 + 2 * tg] = h1;
    }
}

// ----------------------------------------------------------------------------
// Loss: merge per-colblock partials (warp per row), then mean
// ----------------------------------------------------------------------------
__global__ void __launch_bounds__(256) loss_reduce(const float* __restrict__ logits,
                                                   const int* __restrict__ tgt) {
    int row  = blockIdx.x * 8 + (threadIdx.x >> 5);
    int lane = threadIdx.x & 31;
    float m = -3.4e38f, s = 0.f;
    const float* pm = g_pm + (size_t)row * NCB_;
    const float* ps = g_ps + (size_t)row * NCB_;
    for (int j = lane; j < NCB_; j += 32)
        sm_merge(m, s, pm[j], ps[j]);
#pragma unroll
    for (int o = 16; o > 0; o >>= 1) {
        float m2 = __shfl_xor_sync(0xffffffffu, m, o);
        float s2 = __shfl_xor_sync(0xffffffffu, s, o);
        sm_merge(m, s, m2, s2);
    }
    if (lane == 0)
        g_rowloss[row] = -(logits[(size_t)row * V_ + tgt[row]] - m - logf(s));
}

__global__ void finloss_k(float* __restrict__ out) {
    __shared__ float red[256];
    int tid = threadIdx.x;
    float s = 0.f;
    for (int j = tid; j < M_; j += 256) s += g_rowloss[j];
    red[tid] = s; __syncthreads();
    for (int st = 128; st > 0; st >>= 1) { if (tid < st) red[tid] += red[tid + st]; __syncthreads(); }
    if (tid == 0) out[0] = red[0] * (1.f / M_);
}

// ----------------------------------------------------------------------------
// Host driver
// ----------------------------------------------------------------------------
extern "C" void kernel_launch(void* const* d_in, const int* in_sizes, int n_in,
                              void* d_out, int out_size) {
    const float* tok_emb = (const float*)d_in[0];
    const float* pos_emb = (const float*)d_in[1];
    const float* wq      = (const float*)d_in[2];
    const float* wk      = (const float*)d_in[3];
    const float* wv      = (const float*)d_in[4];
    const float* wproj   = (const float*)d_in[5];
    const float* bproj   = (const float*)d_in[6];
    const float* g1      = (const float*)d_in[7];
    const float* b1      = (const float*)d_in[8];
    const float* g2      = (const float*)d_in[9];
    const float* b2      = (const float*)d_in[10];
    const float* wf1     = (const float*)d_in[11];
    const float* bf1     = (const float*)d_in[12];
    const float* wf2     = (const float*)d_in[13];
    const float* bf2     = (const float*)d_in[14];
    const float* gf      = (const float*)d_in[15];
    const float* bf      = (const float*)d_in[16];
    const float* wlm     = (const float*)d_in[17];
    const float* blm     = (const float*)d_in[18];
    const int*   sources = (const int*)d_in[19];
    const int*   targets = (const int*)d_in[20];

    float* out = (float*)d_out;
    const size_t n_logits = (size_t)M_ * V_;

    float  *px;
    __half *ph, *pqkv, *po, *pwqkv, *pff, *pwproj, *pwf1, *pwf2, *pwlm;
    cudaGetSymbolAddress((void**)&px,     g_x);
    cudaGetSymbolAddress((void**)&ph,     g_h);
    cudaGetSymbolAddress((void**)&pqkv,   g_qkv);
    cudaGetSymbolAddress((void**)&po,     g_o);
    cudaGetSymbolAddress((void**)&pwqkv,  g_wqkv);
    cudaGetSymbolAddress((void**)&pff,    g_ff);
    cudaGetSymbolAddress((void**)&pwproj, g_wproj);
    cudaGetSymbolAddress((void**)&pwf1,   g_wf1);
    cudaGetSymbolAddress((void**)&pwf2,   g_wf2);
    cudaGetSymbolAddress((void**)&pwlm,   g_wlm);

    cudaFuncSetAttribute(gemm_h<MODE_PLAIN>, cudaFuncAttributeMaxDynamicSharedMemorySize, GH_SMEM);
    cudaFuncSetAttribute(gemm_h<MODE_HALF>,  cudaFuncAttributeMaxDynamicSharedMemorySize, GH_SMEM);
    cudaFuncSetAttribute(gemm_h<MODE_RELU>,  cudaFuncAttributeMaxDynamicSharedMemorySize, GH_SMEM);
    cudaFuncSetAttribute(gemm_h64_add,       cudaFuncAttributeMaxDynamicSharedMemorySize, GH64_SMEM);

    // 0. transpose + convert weights to [N,K] fp16; pack QKV
    {
        dim3 blk(32, 8);
        for (int i = 0; i < NB_; i++) {
            transp_h<<<dim3(C_ / 32, C_ / 32), blk>>>(wproj + (size_t)i * C_ * C_,
                                                      pwproj + (size_t)i * C_ * C_, C_, C_);
            transp_h<<<dim3(FF_ / 32, C_ / 32), blk>>>(wf1 + (size_t)i * C_ * FF_,
                                                       pwf1 + (size_t)i * C_ * FF_, C_, FF_);
            transp_h<<<dim3(C_ / 32, FF_ / 32), blk>>>(wf2 + (size_t)i * FF_ * C_,
                                                       pwf2 + (size_t)i * FF_ * C_, FF_, C_);
        }
        transp_h<<<dim3(V_ / 32, C_ / 32), blk>>>(wlm, pwlm, C_, V_);
        pack_qkv_all<<<dim3(3 * C_ / 32, C_ / 32, NB_), blk>>>(wq, wk, wv);
    }

    // 1. embedding
    embed_k<<<(M_ * 192) / 256, 256>>>((const float4*)tok_emb, (const float4*)pos_emb, sources);

    // 2. transformer blocks
    for (int i = 0; i < NB_; i++) {
        ln_k<<<M_ / 8, 256>>>(px, ph, g1 + i * C_, b1 + i * C_);

        gemm_h<MODE_HALF><<<dim3(M_ / 128, (3 * C_) / 128), 256, GH_SMEM>>>(
            ph, pwqkv + (size_t)i * 3 * C_ * C_, pqkv, nullptr, C_, 3 * C_);

        attn_flash<<<dim3(T_ / 128, H_, B_), 256>>>();

        gemm_h64_add<<<dim3(M_ / 64, C_ / 128), 256, GH64_SMEM>>>(
            po, pwproj + (size_t)i * C_ * C_, px, bproj + i * C_, C_, C_);

        ln_k<<<M_ / 8, 256>>>(px, ph, g2 + i * C_, b2 + i * C_);

        gemm_h<MODE_RELU><<<dim3(M_ / 128, FF_ / 128), 256, GH_SMEM>>>(
            ph, pwf1 + (size_t)i * C_ * FF_, pff, bf1 + i * FF_, C_, FF_);

        gemm_h64_add<<<dim3(M_ / 64, C_ / 128), 256, GH64_SMEM>>>(
            pff, pwf2 + (size_t)i * FF_ * C_, px, bf2 + i * C_, FF_, C_);
    }

    // 3. final LN + LM head -> d_out (+ softmax partials in epilogue)
    ln_k<<<M_ / 8, 256>>>(px, ph, gf, bf);
    gemm_h<MODE_PLAIN><<<dim3(M_ / 128, V_ / 128), 256, GH_SMEM>>>(
        ph, pwlm, out, blm, C_, V_);

    // 4. loss: merge partials + mean
    loss_reduce<<<M_ / 8, 256>>>(out, targets);
    if ((size_t)out_size > n_logits)
        finloss_k<<<1, 256>>>(out + n_logits);
}

// round 16
// speedup vs baseline: 1.1310x; 1.1310x over previous
#include <cuda_runtime.h>
#include <cuda_fp16.h>
#include <cstdint>
#include <math.h>

// Problem constants
#define V_   32000
#define C_   768
#define T_   1024
#define H_   12
#define HS_  64
#define FF_  9216
#define NB_  3
#define B_   4
#define M_   (B_ * T_)
#define EPS_ 1e-5f
#define SCALE_ 0.03608439182435161f   // 768^-0.5
#define NCB_  (V_ / 128)              // 250 column blocks in LM head

// FP16 GEMM tiling: CTA 128x128x64, 8 warps of 64x32, 2-stage cp.async
#define AH_STR 72                       // halves (144B rows, ldmatrix conflict-free)
#define BH_STR 136
#define AH_SZ  (128 * AH_STR)           // per stage
#define BH_SZ  (64 * BH_STR)
#define GH_SMEM (2 * (AH_SZ + BH_SZ) * 2)   // 71680 bytes

// BM=64 variant (proj / FF2): CTA 64x128x64, 8 warps of 32x32
#define AH64_SZ (64 * AH_STR)
#define GH64_SMEM (2 * (AH64_SZ + BH_SZ) * 2)  // 53248 bytes

// Attention: fp16 tiles, stride 72 halves; Q tile = 128 rows, KV tile = 64
#define AST 72

// Epilogue modes
#define MODE_PLAIN 0     // float out (streaming stores) + softmax partials (LM head)
#define MODE_ADD   1     // float out += residual
#define MODE_HALF  2     // half out
#define MODE_RELU  3     // half out, relu

// ----------------------------------------------------------------------------
// Scratch
// ----------------------------------------------------------------------------
__device__ float  g_x[M_ * C_];
__device__ __half g_h[M_ * C_];
__device__ __half g_qkv[M_ * 3 * C_];
__device__ __half g_o[M_ * C_];
__device__ __half g_wqkv[NB_ * C_ * 3 * C_];        // [blk][K=768][N=2304]
__device__ __half g_wproj[NB_ * C_ * C_];
__device__ __half g_wf1[(size_t)NB_ * C_ * FF_];
__device__ __half g_wf2[(size_t)NB_ * FF_ * C_];
__device__ __half g_wlm[(size_t)C_ * V_];
__device__ __half g_ff[(size_t)M_ * FF_];
__device__ float  g_pm[(size_t)M_ * NCB_];
__device__ float  g_ps[(size_t)M_ * NCB_];
__device__ float  g_rowloss[M_];

// ----------------------------------------------------------------------------
// PTX helpers
// ----------------------------------------------------------------------------
#define CP16(dst, src) asm volatile("cp.async.cg.shared.global [%0], [%1], 16;\n" :: "r"(dst), "l"(src) : "memory")
#define CP_COMMIT() asm volatile("cp.async.commit_group;\n" ::: "memory")

__device__ __forceinline__ void mma_f16(float* c, const uint32_t* a, uint32_t b0, uint32_t b1) {
    asm volatile("mma.sync.aligned.m16n8k16.row.col.f32.f16.f16.f32 "
                 "{%0,%1,%2,%3}, {%4,%5,%6,%7}, {%8,%9}, {%0,%1,%2,%3};"
                 : "+f"(c[0]), "+f"(c[1]), "+f"(c[2]), "+f"(c[3])
                 : "r"(a[0]), "r"(a[1]), "r"(a[2]), "r"(a[3]), "r"(b0), "r"(b1));
}

#define LDSM_X4(r, addr) \
    asm volatile("ldmatrix.sync.aligned.m8n8.x4.shared.b16 {%0,%1,%2,%3}, [%4];" \
                 : "=r"((r)[0]), "=r"((r)[1]), "=r"((r)[2]), "=r"((r)[3]) : "r"(addr))
#define LDSM_X4_T(r, addr) \
    asm volatile("ldmatrix.sync.aligned.m8n8.x4.trans.shared.b16 {%0,%1,%2,%3}, [%4];" \
                 : "=r"((r)[0]), "=r"((r)[1]), "=r"((r)[2]), "=r"((r)[3]) : "r"(addr))

__device__ __forceinline__ void sm_merge(float& m, float& s, float m2, float s2) {
    float mm = fmaxf(m, m2);
    s = s * __expf(m - mm) + s2 * __expf(m2 - mm);
    m = mm;
}

// ----------------------------------------------------------------------------
// Weight convert fp32 -> fp16
// ----------------------------------------------------------------------------
__global__ void tohalf_k(const float4* __restrict__ in, uint2* __restrict__ out, size_t n4) {
    size_t i = (size_t)blockIdx.x * blockDim.x + threadIdx.x;
    if (i < n4) {
        float4 v = in[i];
        __half2 h0 = __floats2half2_rn(v.x, v.y);
        __half2 h1 = __floats2half2_rn(v.z, v.w);
        out[i] = make_uint2(*(uint32_t*)&h0, *(uint32_t*)&h1);
    }
}

// ----------------------------------------------------------------------------
// Embedding
// ----------------------------------------------------------------------------
__global__ void embed_k(const float4* __restrict__ tok, const float4* __restrict__ pos,
                        const int* __restrict__ src) {
    int idx = blockIdx.x * blockDim.x + threadIdx.x;
    int row = idx / 192;
    int c4  = idx - row * 192;
    int t   = row % T_;
    float4 a = tok[(size_t)src[row] * 192 + c4];
    float4 p = pos[t * 192 + c4];
    ((float4*)g_x)[idx] = make_float4(a.x + p.x, a.y + p.y, a.z + p.z, a.w + p.w);
}

// ----------------------------------------------------------------------------
// LayerNorm: warp per row, fp16 out
// ----------------------------------------------------------------------------
__global__ void __launch_bounds__(256) ln_k(const float* __restrict__ in, __half* __restrict__ out,
                                            const float* __restrict__ g, const float* __restrict__ b) {
    int warp = threadIdx.x >> 5, lane = threadIdx.x & 31;
    int row = blockIdx.x * 8 + warp;
    const float4* x4 = (const float4*)(in + (size_t)row * C_);

    float4 v[6];
    float s = 0.f, s2 = 0.f;
#pragma unroll
    for (int i = 0; i < 6; i++) {
        v[i] = x4[lane + 32 * i];
        s  += v[i].x + v[i].y + v[i].z + v[i].w;
        s2 += v[i].x * v[i].x + v[i].y * v[i].y + v[i].z * v[i].z + v[i].w * v[i].w;
    }
#pragma unroll
    for (int o = 16; o > 0; o >>= 1) {
        s  += __shfl_xor_sync(0xffffffffu, s, o);
        s2 += __shfl_xor_sync(0xffffffffu, s2, o);
    }
    float mean = s * (1.f / C_);
    float var  = s2 * (1.f / C_) - mean * mean;
    float inv  = rsqrtf(var + EPS_);

    const float4* g4 = (const float4*)g;
    const float4* b4 = (const float4*)b;
    uint2* o4 = (uint2*)(out + (size_t)row * C_);
#pragma unroll
    for (int i = 0; i < 6; i++) {
        float4 gg = g4[lane + 32 * i], bb = b4[lane + 32 * i];
        __half2 h0 = __floats2half2_rn((v[i].x - mean) * inv * gg.x + bb.x,
                                       (v[i].y - mean) * inv * gg.y + bb.y);
        __half2 h1 = __floats2half2_rn((v[i].z - mean) * inv * gg.z + bb.z,
                                       (v[i].w - mean) * inv * gg.w + bb.w);
        o4[lane + 32 * i] = make_uint2(*(uint32_t*)&h0, *(uint32_t*)&h1);
    }
}

// ----------------------------------------------------------------------------
// Pack wq/wk/wv for ALL blocks into [blk][K=768][N=2304] fp16
// ----------------------------------------------------------------------------
__global__ void pack_qkv_all(const float* __restrict__ wq, const float* __restrict__ wk,
                             const float* __restrict__ wv) {
    int idx = blockIdx.x * blockDim.x + threadIdx.x;
    if (idx >= NB_ * C_ * 3 * C_) return;
    int blk = idx / (C_ * 3 * C_);
    int rem = idx - blk * (C_ * 3 * C_);
    int c   = rem / (3 * C_);
    int col = rem - c * (3 * C_);
    const float* w = (col < C_) ? wq : (col < 2 * C_ ? wk : wv);
    int j = col % C_;
    int h = j / HS_, d = j % HS_;
    g_wqkv[idx] = __float2half_rn(w[(size_t)blk * H_ * C_ * HS_ + ((size_t)h * C_ + c) * HS_ + d]);
}

// ----------------------------------------------------------------------------
// FP16 GEMM (BM=128): C[M,N] = A[M,K] @ B[K,N], BK=64, 2-stage cp.async.
// MODE_PLAIN: streaming logits stores + per-row online-softmax partials.
// ----------------------------------------------------------------------------
__device__ __forceinline__ void gh_load(uint32_t sa, uint32_t sb,
                                        const __half* Ag, const __half* Bg,
                                        int K, int N, int tid) {
#pragma unroll
    for (int i = 0; i < 4; i++) {
        int idx = tid + i * 256;
        int row = idx >> 3, q = idx & 7;
        CP16(sa + (uint32_t)((row * AH_STR + q * 8) * 2), Ag + (size_t)row * K + q * 8);
    }
#pragma unroll
    for (int i = 0; i < 4; i++) {
        int idx = tid + i * 256;
        int row = idx >> 4, q = idx & 15;
        CP16(sb + (uint32_t)((row * BH_STR + q * 8) * 2), Bg + (size_t)row * N + q * 8);
    }
    CP_COMMIT();
}

template<int MODE>
__global__ void __launch_bounds__(256)
gemm_h(const __half* __restrict__ A, const __half* __restrict__ B,
       void* __restrict__ Cv, const float* __restrict__ bias,
       int K, int N) {
    extern __shared__ __half hs[];
    uint32_t s_u = (uint32_t)__cvta_generic_to_shared(hs);
    uint32_t a_b[2] = { s_u, s_u + (uint32_t)((AH_SZ + BH_SZ) * 2) };
    uint32_t b_b[2] = { a_b[0] + AH_SZ * 2, a_b[1] + AH_SZ * 2 };

    int tid  = threadIdx.x;
    int warp = tid >> 5, lane = tid & 31;
    int brow = blockIdx.x * 128;
    int bcol = blockIdx.y * 128;
    int wm = (warp & 1) * 64, wn = (warp >> 1) * 32;
    int gid = lane >> 2, tg = lane & 3;
    int l16 = lane & 15, lh = lane >> 4;

    float acc[4][4][4];
#pragma unroll
    for (int i = 0; i < 4; i++)
#pragma unroll
        for (int j = 0; j < 4; j++)
#pragma unroll
            for (int r = 0; r < 4; r++) acc[i][j][r] = 0.f;

    const __half* Abase = A + (size_t)brow * K;
    const __half* Bbase = B + bcol;

    int nk = K / 64;
    gh_load(a_b[0], b_b[0], Abase, Bbase, K, N, tid);

    for (int kt = 0; kt < nk; kt++) {
        int s = kt & 1;
        if (kt + 1 < nk) {
            gh_load(a_b[s ^ 1], b_b[s ^ 1], Abase + (kt + 1) * 64,
                    Bbase + (size_t)(kt + 1) * 64 * N, K, N, tid);
            asm volatile("cp.async.wait_group 1;\n" ::: "memory");
        } else {
            asm volatile("cp.async.wait_group 0;\n" ::: "memory");
        }
        __syncthreads();

#pragma unroll
        for (int ks = 0; ks < 4; ks++) {
            uint32_t af[4][4], bfr[2][4];
#pragma unroll
            for (int mt = 0; mt < 4; mt++) {
                uint32_t addr = a_b[s] + (uint32_t)(((wm + mt * 16 + l16) * AH_STR
                                                    + ks * 16 + lh * 8) * 2);
                LDSM_X4(af[mt], addr);
            }
#pragma unroll
            for (int np = 0; np < 2; np++) {
                uint32_t addr = b_b[s] + (uint32_t)(((ks * 16 + l16) * BH_STR
                                                    + wn + np * 16 + lh * 8) * 2);
                LDSM_X4_T(bfr[np], addr);
            }
#pragma unroll
            for (int mt = 0; mt < 4; mt++)
#pragma unroll
                for (int nt = 0; nt < 4; nt++)
                    mma_f16(acc[mt][nt], af[mt], bfr[nt >> 1][(nt & 1) * 2],
                            bfr[nt >> 1][(nt & 1) * 2 + 1]);
        }
        __syncthreads();
    }

    // ---------------- epilogue ----------------
    if (MODE == MODE_HALF || MODE == MODE_RELU || MODE == MODE_ADD) {
#pragma unroll
        for (int mt = 0; mt < 4; mt++) {
            int r0 = brow + wm + mt * 16 + gid;
#pragma unroll
            for (int nt = 0; nt < 4; nt++) {
                int c0 = bcol + wn + nt * 8 + tg * 2;
                float b0v = bias ? bias[c0] : 0.f;
                float b1v = bias ? bias[c0 + 1] : 0.f;
                float v0 = acc[mt][nt][0] + b0v, v1 = acc[mt][nt][1] + b1v;
                float v2 = acc[mt][nt][2] + b0v, v3 = acc[mt][nt][3] + b1v;
                if (MODE == MODE_HALF || MODE == MODE_RELU) {
                    if (MODE == MODE_RELU) {
                        v0 = fmaxf(v0, 0.f); v1 = fmaxf(v1, 0.f);
                        v2 = fmaxf(v2, 0.f); v3 = fmaxf(v3, 0.f);
                    }
                    __half* ph = (__half*)Cv;
                    *(__half2*)(ph + (size_t)r0 * N + c0)       = __floats2half2_rn(v0, v1);
                    *(__half2*)(ph + (size_t)(r0 + 8) * N + c0) = __floats2half2_rn(v2, v3);
                } else {
                    float* pf = (float*)Cv;
                    float* p0 = pf + (size_t)r0 * N + c0;
                    float* p1 = pf + (size_t)(r0 + 8) * N + c0;
                    v0 += p0[0]; v1 += p0[1]; v2 += p1[0]; v3 += p1[1];
                    p0[0] = v0; p0[1] = v1; p1[0] = v2; p1[1] = v3;
                }
            }
        }
    } else {
        // MODE_PLAIN: streaming logits stores + per-row softmax partials
        float bb0[4], bb1[4];
#pragma unroll
        for (int nt = 0; nt < 4; nt++) {
            int c0 = bcol + wn + nt * 8 + tg * 2;
            bb0[nt] = bias ? bias[c0] : 0.f;
            bb1[nt] = bias ? bias[c0 + 1] : 0.f;
        }
        float rm[4][2], rs[4][2];
#pragma unroll
        for (int mt = 0; mt < 4; mt++) { rm[mt][0] = rm[mt][1] = -3.4e38f; rs[mt][0] = rs[mt][1] = 0.f; }

        float* pf = (float*)Cv;
#pragma unroll
        for (int mt = 0; mt < 4; mt++) {
            int r0 = brow + wm + mt * 16 + gid;
#pragma unroll
            for (int nt = 0; nt < 4; nt++) {
                int c0 = bcol + wn + nt * 8 + tg * 2;
                float v0 = acc[mt][nt][0] + bb0[nt], v1 = acc[mt][nt][1] + bb1[nt];
                float v2 = acc[mt][nt][2] + bb0[nt], v3 = acc[mt][nt][3] + bb1[nt];
                __stcs((float2*)(pf + (size_t)r0 * N + c0),       make_float2(v0, v1));
                __stcs((float2*)(pf + (size_t)(r0 + 8) * N + c0), make_float2(v2, v3));
                rm[mt][0] = fmaxf(rm[mt][0], fmaxf(v0, v1));
                rm[mt][1] = fmaxf(rm[mt][1], fmaxf(v2, v3));
            }
        }
#pragma unroll
        for (int mt = 0; mt < 4; mt++)
#pragma unroll
            for (int nt = 0; nt < 4; nt++) {
                rs[mt][0] += __expf(acc[mt][nt][0] + bb0[nt] - rm[mt][0])
                           + __expf(acc[mt][nt][1] + bb1[nt] - rm[mt][0]);
                rs[mt][1] += __expf(acc[mt][nt][2] + bb0[nt] - rm[mt][1])
                           + __expf(acc[mt][nt][3] + bb1[nt] - rm[mt][1]);
            }
#pragma unroll
        for (int mt = 0; mt < 4; mt++)
#pragma unroll
            for (int hf = 0; hf < 2; hf++) {
#pragma unroll
                for (int o = 1; o <= 2; o <<= 1) {
                    float m2 = __shfl_xor_sync(0xffffffffu, rm[mt][hf], o);
                    float s2 = __shfl_xor_sync(0xffffffffu, rs[mt][hf], o);
                    sm_merge(rm[mt][hf], rs[mt][hf], m2, s2);
                }
            }
        __syncthreads();
        float* fs = (float*)hs;
        int wg = warp >> 1;
        if (tg == 0) {
#pragma unroll
            for (int mt = 0; mt < 4; mt++)
#pragma unroll
                for (int hf = 0; hf < 2; hf++) {
                    int rl = wm + mt * 16 + gid + hf * 8;
                    fs[rl * 4 + wg]       = rm[mt][hf];
                    fs[512 + rl * 4 + wg] = rs[mt][hf];
                }
        }
        __syncthreads();
        if (tid < 128) {
            float m = fs[tid * 4], s = fs[512 + tid * 4];
            sm_merge(m, s, fs[tid * 4 + 1], fs[512 + tid * 4 + 1]);
            sm_merge(m, s, fs[tid * 4 + 2], fs[512 + tid * 4 + 2]);
            sm_merge(m, s, fs[tid * 4 + 3], fs[512 + tid * 4 + 3]);
            size_t off = (size_t)(brow + tid) * gridDim.y + blockIdx.y;
            g_pm[off] = m;
            g_ps[off] = s;
        }
    }
}

// ----------------------------------------------------------------------------
// FP16 GEMM (BM=64, MODE_ADD): proj / FF2. 8 warps of 32x32.
// ----------------------------------------------------------------------------
__device__ __forceinline__ void gh_load64(uint32_t sa, uint32_t sb,
                                          const __half* Ag, const __half* Bg,
                                          int K, int N, int tid) {
#pragma unroll
    for (int i = 0; i < 2; i++) {
        int idx = tid + i * 256;
        int row = idx >> 3, q = idx & 7;
        CP16(sa + (uint32_t)((row * AH_STR + q * 8) * 2), Ag + (size_t)row * K + q * 8);
    }
#pragma unroll
    for (int i = 0; i < 4; i++) {
        int idx = tid + i * 256;
        int row = idx >> 4, q = idx & 15;
        CP16(sb + (uint32_t)((row * BH_STR + q * 8) * 2), Bg + (size_t)row * N + q * 8);
    }
    CP_COMMIT();
}

__global__ void __launch_bounds__(256)
gemm_h64_add(const __half* __restrict__ A, const __half* __restrict__ B,
             float* __restrict__ Cf, const float* __restrict__ bias,
             int K, int N) {
    extern __shared__ __half hs[];
    uint32_t s_u = (uint32_t)__cvta_generic_to_shared(hs);
    uint32_t a_b[2] = { s_u, s_u + (uint32_t)((AH64_SZ + BH_SZ) * 2) };
    uint32_t b_b[2] = { a_b[0] + AH64_SZ * 2, a_b[1] + AH64_SZ * 2 };

    int tid  = threadIdx.x;
    int warp = tid >> 5, lane = tid & 31;
    int brow = blockIdx.x * 64;
    int bcol = blockIdx.y * 128;
    int wm = (warp & 1) * 32, wn = (warp >> 1) * 32;
    int gid = lane >> 2, tg = lane & 3;
    int l16 = lane & 15, lh = lane >> 4;

    float acc[2][4][4];
#pragma unroll
    for (int i = 0; i < 2; i++)
#pragma unroll
        for (int j = 0; j < 4; j++)
#pragma unroll
            for (int r = 0; r < 4; r++) acc[i][j][r] = 0.f;

    const __half* Abase = A + (size_t)brow * K;
    const __half* Bbase = B + bcol;

    int nk = K / 64;
    gh_load64(a_b[0], b_b[0], Abase, Bbase, K, N, tid);

    for (int kt = 0; kt < nk; kt++) {
        int s = kt & 1;
        if (kt + 1 < nk) {
            gh_load64(a_b[s ^ 1], b_b[s ^ 1], Abase + (kt + 1) * 64,
                      Bbase + (size_t)(kt + 1) * 64 * N, K, N, tid);
            asm volatile("cp.async.wait_group 1;\n" ::: "memory");
        } else {
            asm volatile("cp.async.wait_group 0;\n" ::: "memory");
        }
        __syncthreads();

#pragma unroll
        for (int ks = 0; ks < 4; ks++) {
            uint32_t af[2][4], bfr[2][4];
#pragma unroll
            for (int mt = 0; mt < 2; mt++) {
                uint32_t addr = a_b[s] + (uint32_t)(((wm + mt * 16 + l16) * AH_STR
                                                    + ks * 16 + lh * 8) * 2);
                LDSM_X4(af[mt], addr);
            }
#pragma unroll
            for (int np = 0; np < 2; np++) {
                uint32_t addr = b_b[s] + (uint32_t)(((ks * 16 + l16) * BH_STR
                                                    + wn + np * 16 + lh * 8) * 2);
                LDSM_X4_T(bfr[np], addr);
            }
#pragma unroll
            for (int mt = 0; mt < 2; mt++)
#pragma unroll
                for (int nt = 0; nt < 4; nt++)
                    mma_f16(acc[mt][nt], af[mt], bfr[nt >> 1][(nt & 1) * 2],
                            bfr[nt >> 1][(nt & 1) * 2 + 1]);
        }
        __syncthreads();
    }

#pragma unroll
    for (int mt = 0; mt < 2; mt++) {
        int r0 = brow + wm + mt * 16 + gid;
#pragma unroll
        for (int nt = 0; nt < 4; nt++) {
            int c0 = bcol + wn + nt * 8 + tg * 2;
            float b0v = bias[c0], b1v = bias[c0 + 1];
            float* p0 = Cf + (size_t)r0 * N + c0;
            float* p1 = Cf + (size_t)(r0 + 8) * N + c0;
            p0[0] = acc[mt][nt][0] + b0v + p0[0];
            p0[1] = acc[mt][nt][1] + b1v + p0[1];
            p1[0] = acc[mt][nt][2] + b0v + p1[0];
            p1[1] = acc[mt][nt][3] + b1v + p1[1];
        }
    }
}

// ----------------------------------------------------------------------------
// FP16 flash attention: qtile 128, 8 warps, P in registers (round-14 proven)
// ----------------------------------------------------------------------------
__global__ void __launch_bounds__(256) attn_flash() {
    __shared__ __half ahs[(128 + 64 + 64) * AST];
    __half* Qs = ahs;
    __half* Ks = ahs + 128 * AST;
    __half* Vs = ahs + (128 + 64) * AST;
    uint32_t qs_u = (uint32_t)__cvta_generic_to_shared(Qs);
    uint32_t ks_u = qs_u + 128 * AST * 2;
    uint32_t vs_u = qs_u + (128 + 64) * AST * 2;

    int qi = blockIdx.x, h = blockIdx.y, b = blockIdx.z;
    int q0 = qi * 128;
    int tid = threadIdx.x, lane = tid & 31, w = tid >> 5;
    int gid = lane >> 2, tg = lane & 3;
    int l16 = lane & 15, lh = lane >> 4;
    size_t base = (size_t)(b * T_) * (3 * C_);
    int hoff = h * HS_;

    for (int i = tid; i < 128 * 8; i += 256) {
        int r = i >> 3, c8 = (i & 7) << 3;
        *(uint4*)&Qs[r * AST + c8] =
            *(const uint4*)&g_qkv[base + (size_t)(q0 + r) * 3 * C_ + hoff + c8];
    }
    __syncthreads();

    uint32_t qf[4][4];
#pragma unroll
    for (int ks = 0; ks < 4; ks++)
        LDSM_X4(qf[ks], qs_u + (uint32_t)(((w * 16 + l16) * AST + ks * 16 + lh * 8) * 2));

    float m0 = -1e30f, m1 = -1e30f, l0 = 0.f, l1 = 0.f;
    float acc_o[8][4];
#pragma unroll
    for (int nt = 0; nt < 8; nt++)
#pragma unroll
        for (int r = 0; r < 4; r++) acc_o[nt][r] = 0.f;

    int row0 = q0 + w * 16 + gid;
    int row1 = row0 + 8;

    for (int j0 = 0; j0 < q0 + 128; j0 += 64) {
        __syncthreads();
        for (int i = tid; i < 64 * 8; i += 256) {
            int r = i >> 3, c8 = (i & 7) << 3;
            size_t rb = base + (size_t)(j0 + r) * 3 * C_ + hoff + c8;
            *(uint4*)&Ks[r * AST + c8] = *(const uint4*)&g_qkv[rb + C_];
            *(uint4*)&Vs[r * AST + c8] = *(const uint4*)&g_qkv[rb + 2 * C_];
        }
        __syncthreads();

        float sc[8][4];
#pragma unroll
        for (int nt = 0; nt < 8; nt++)
#pragma unroll
            for (int r = 0; r < 4; r++) sc[nt][r] = 0.f;
#pragma unroll
        for (int ks = 0; ks < 4; ks++) {
            uint32_t bk[4][4];
#pragma unroll
            for (int np = 0; np < 4; np++)
                LDSM_X4(bk[np], ks_u + (uint32_t)(((np * 16 + l16) * AST + ks * 16 + lh * 8) * 2));
#pragma unroll
            for (int nt = 0; nt < 8; nt++)
                mma_f16(sc[nt], qf[ks], bk[nt >> 1][nt & 1], bk[nt >> 1][(nt & 1) + 2]);
        }

        bool needmask = (j0 + 63 > row0);
#pragma unroll
        for (int nt = 0; nt < 8; nt++) {
            sc[nt][0] *= SCALE_; sc[nt][1] *= SCALE_;
            sc[nt][2] *= SCALE_; sc[nt][3] *= SCALE_;
            if (needmask) {
                int jg = j0 + nt * 8 + tg * 2;
                if (jg > row0)     sc[nt][0] = -1e30f;
                if (jg + 1 > row0) sc[nt][1] = -1e30f;
                if (jg > row1)     sc[nt][2] = -1e30f;
                if (jg + 1 > row1) sc[nt][3] = -1e30f;
            }
        }

        float mx0 = -1e30f, mx1 = -1e30f;
#pragma unroll
        for (int nt = 0; nt < 8; nt++) {
            mx0 = fmaxf(mx0, fmaxf(sc[nt][0], sc[nt][1]));
            mx1 = fmaxf(mx1, fmaxf(sc[nt][2], sc[nt][3]));
        }
        mx0 = fmaxf(mx0, __shfl_xor_sync(0xffffffffu, mx0, 1));
        mx0 = fmaxf(mx0, __shfl_xor_sync(0xffffffffu, mx0, 2));
        mx1 = fmaxf(mx1, __shfl_xor_sync(0xffffffffu, mx1, 1));
        mx1 = fmaxf(mx1, __shfl_xor_sync(0xffffffffu, mx1, 2));

        float mn0 = fmaxf(m0, mx0), mn1 = fmaxf(m1, mx1);
        float a0 = __expf(m0 - mn0), a1 = __expf(m1 - mn1);
        m0 = mn0; m1 = mn1;

        float s0 = 0.f, s1 = 0.f;
#pragma unroll
        for (int nt = 0; nt < 8; nt++) {
            float p0 = __expf(sc[nt][0] - mn0), p1 = __expf(sc[nt][1] - mn0);
            float p2 = __expf(sc[nt][2] - mn1), p3 = __expf(sc[nt][3] - mn1);
            s0 += p0 + p1; s1 += p2 + p3;
            sc[nt][0] = p0; sc[nt][1] = p1; sc[nt][2] = p2; sc[nt][3] = p3;
        }
        s0 += __shfl_xor_sync(0xffffffffu, s0, 1);
        s0 += __shfl_xor_sync(0xffffffffu, s0, 2);
        s1 += __shfl_xor_sync(0xffffffffu, s1, 1);
        s1 += __shfl_xor_sync(0xffffffffu, s1, 2);
        l0 = l0 * a0 + s0;
        l1 = l1 * a1 + s1;

#pragma unroll
        for (int nt = 0; nt < 8; nt++) {
            acc_o[nt][0] *= a0; acc_o[nt][1] *= a0;
            acc_o[nt][2] *= a1; acc_o[nt][3] *= a1;
        }

#pragma unroll
        for (int ks = 0; ks < 4; ks++) {
            uint32_t pf[4];
            __half2 t0 = __floats2half2_rn(sc[2 * ks][0],     sc[2 * ks][1]);
            __half2 t1 = __floats2half2_rn(sc[2 * ks][2],     sc[2 * ks][3]);
            __half2 t2 = __floats2half2_rn(sc[2 * ks + 1][0], sc[2 * ks + 1][1]);
            __half2 t3 = __floats2half2_rn(sc[2 * ks + 1][2], sc[2 * ks + 1][3]);
            pf[0] = *(uint32_t*)&t0; pf[1] = *(uint32_t*)&t1;
            pf[2] = *(uint32_t*)&t2; pf[3] = *(uint32_t*)&t3;
            uint32_t bv[4][4];
#pragma unroll
            for (int np = 0; np < 4; np++)
                LDSM_X4_T(bv[np], vs_u + (uint32_t)(((ks * 16 + l16) * AST + np * 16 + lh * 8) * 2));
#pragma unroll
            for (int nt = 0; nt < 8; nt++)
                mma_f16(acc_o[nt], pf, bv[nt >> 1][(nt & 1) * 2], bv[nt >> 1][(nt & 1) * 2 + 1]);
        }
    }

    float i0 = 1.f / l0, i1 = 1.f / l1;
#pragma unroll
    for (int nt = 0; nt < 8; nt++) {
        __half2 h0 = __floats2half2_rn(acc_o[nt][0] * i0, acc_o[nt][1] * i0);
        __half2 h1 = __floats2half2_rn(acc_o[nt][2] * i1, acc_o[nt][3] * i1);
        *(__half2*)&g_o[(size_t)(b * T_ + row0) * C_ + hoff + nt * 8 + 2 * tg] = h0;
        *(__half2*)&g_o[(size_t)(b * T_ + row1) * C_ + hoff + nt * 8 + 2 * tg] = h1;
    }
}

// ----------------------------------------------------------------------------
// Loss: merge per-colblock partials (warp per row), then mean
// ----------------------------------------------------------------------------
__global__ void __launch_bounds__(256) loss_reduce(const float* __restrict__ logits,
                                                   const int* __restrict__ tgt) {
    int row  = blockIdx.x * 8 + (threadIdx.x >> 5);
    int lane = threadIdx.x & 31;
    float m = -3.4e38f, s = 0.f;
    const float* pm = g_pm + (size_t)row * NCB_;
    const float* ps = g_ps + (size_t)row * NCB_;
    for (int j = lane; j < NCB_; j += 32)
        sm_merge(m, s, pm[j], ps[j]);
#pragma unroll
    for (int o = 16; o > 0; o >>= 1) {
        float m2 = __shfl_xor_sync(0xffffffffu, m, o);
        float s2 = __shfl_xor_sync(0xffffffffu, s, o);
        sm_merge(m, s, m2, s2);
    }
    if (lane == 0)
        g_rowloss[row] = -(logits[(size_t)row * V_ + tgt[row]] - m - logf(s));
}

__global__ void finloss_k(float* __restrict__ out) {
    __shared__ float red[256];
    int tid = threadIdx.x;
    float s = 0.f;
    for (int j = tid; j < M_; j += 256) s += g_rowloss[j];
    red[tid] = s; __syncthreads();
    for (int st = 128; st > 0; st >>= 1) { if (tid < st) red[tid] += red[tid + st]; __syncthreads(); }
    if (tid == 0) out[0] = red[0] * (1.f / M_);
}

// ----------------------------------------------------------------------------
// Host driver
// ----------------------------------------------------------------------------
extern "C" void kernel_launch(void* const* d_in, const int* in_sizes, int n_in,
                              void* d_out, int out_size) {
    const float* tok_emb = (const float*)d_in[0];
    const float* pos_emb = (const float*)d_in[1];
    const float* wq      = (const float*)d_in[2];
    const float* wk      = (const float*)d_in[3];
    const float* wv      = (const float*)d_in[4];
    const float* wproj   = (const float*)d_in[5];
    const float* bproj   = (const float*)d_in[6];
    const float* g1      = (const float*)d_in[7];
    const float* b1      = (const float*)d_in[8];
    const float* g2      = (const float*)d_in[9];
    const float* b2      = (const float*)d_in[10];
    const float* wf1     = (const float*)d_in[11];
    const float* bf1     = (const float*)d_in[12];
    const float* wf2     = (const float*)d_in[13];
    const float* bf2     = (const float*)d_in[14];
    const float* gf      = (const float*)d_in[15];
    const float* bf      = (const float*)d_in[16];
    const float* wlm     = (const float*)d_in[17];
    const float* blm     = (const float*)d_in[18];
    const int*   sources = (const int*)d_in[19];
    const int*   targets = (const int*)d_in[20];

    float* out = (float*)d_out;
    const size_t n_logits = (size_t)M_ * V_;

    float  *px;
    __half *ph, *pqkv, *po, *pwqkv, *pff, *pwproj, *pwf1, *pwf2, *pwlm;
    cudaGetSymbolAddress((void**)&px,     g_x);
    cudaGetSymbolAddress((void**)&ph,     g_h);
    cudaGetSymbolAddress((void**)&pqkv,   g_qkv);
    cudaGetSymbolAddress((void**)&po,     g_o);
    cudaGetSymbolAddress((void**)&pwqkv,  g_wqkv);
    cudaGetSymbolAddress((void**)&pff,    g_ff);
    cudaGetSymbolAddress((void**)&pwproj, g_wproj);
    cudaGetSymbolAddress((void**)&pwf1,   g_wf1);
    cudaGetSymbolAddress((void**)&pwf2,   g_wf2);
    cudaGetSymbolAddress((void**)&pwlm,   g_wlm);

    cudaFuncSetAttribute(gemm_h<MODE_PLAIN>, cudaFuncAttributeMaxDynamicSharedMemorySize, GH_SMEM);
    cudaFuncSetAttribute(gemm_h<MODE_HALF>,  cudaFuncAttributeMaxDynamicSharedMemorySize, GH_SMEM);
    cudaFuncSetAttribute(gemm_h<MODE_RELU>,  cudaFuncAttributeMaxDynamicSharedMemorySize, GH_SMEM);
    cudaFuncSetAttribute(gemm_h64_add,       cudaFuncAttributeMaxDynamicSharedMemorySize, GH64_SMEM);

    // 0. convert weights to fp16 (linear copies, B stays [K,N]); pack QKV
    {
        size_t n4;
        n4 = (size_t)NB_ * C_ * C_ / 4;
        tohalf_k<<<(unsigned)((n4 + 255) / 256), 256>>>((const float4*)wproj, (uint2*)pwproj, n4);
        n4 = (size_t)NB_ * C_ * FF_ / 4;
        tohalf_k<<<(unsigned)((n4 + 255) / 256), 256>>>((const float4*)wf1, (uint2*)pwf1, n4);
        tohalf_k<<<(unsigned)((n4 + 255) / 256), 256>>>((const float4*)wf2, (uint2*)pwf2, n4);
        n4 = (size_t)C_ * V_ / 4;
        tohalf_k<<<(unsigned)((n4 + 255) / 256), 256>>>((const float4*)wlm, (uint2*)pwlm, n4);
        pack_qkv_all<<<(NB_ * C_ * 3 * C_ + 255) / 256, 256>>>(wq, wk, wv);
    }

    // 1. embedding
    embed_k<<<(M_ * 192) / 256, 256>>>((const float4*)tok_emb, (const float4*)pos_emb, sources);

    // 2. transformer blocks
    for (int i = 0; i < NB_; i++) {
        ln_k<<<M_ / 8, 256>>>(px, ph, g1 + i * C_, b1 + i * C_);

        gemm_h<MODE_HALF><<<dim3(M_ / 128, (3 * C_) / 128), 256, GH_SMEM>>>(
            ph, pwqkv + (size_t)i * C_ * 3 * C_, pqkv, nullptr, C_, 3 * C_);

        attn_flash<<<dim3(T_ / 128, H_, B_), 256>>>();

        gemm_h64_add<<<dim3(M_ / 64, C_ / 128), 256, GH64_SMEM>>>(
            po, pwproj + (size_t)i * C_ * C_, px, bproj + i * C_, C_, C_);

        ln_k<<<M_ / 8, 256>>>(px, ph, g2 + i * C_, b2 + i * C_);

        gemm_h<MODE_RELU><<<dim3(M_ / 128, FF_ / 128), 256, GH_SMEM>>>(
            ph, pwf1 + (size_t)i * C_ * FF_, pff, bf1 + i * FF_, C_, FF_);

        gemm_h64_add<<<dim3(M_ / 64, C_ / 128), 256, GH64_SMEM>>>(
            pff, pwf2 + (size_t)i * FF_ * C_, px, bf2 + i * C_, FF_, C_);
    }

    // 3. final LN + LM head -> d_out (+ softmax partials, streaming stores)
    ln_k<<<M_ / 8, 256>>>(px, ph, gf, bf);
    gemm_h<MODE_PLAIN><<<dim3(M_ / 128, V_ / 128), 256, GH_SMEM>>>(
        ph, pwlm, out, blm, C_, V_);

    // 4. loss: merge partials + mean
    loss_reduce<<<M_ / 8, 256>>>(out, targets);
    if ((size_t)out_size > n_logits)
        finloss_k<<<1, 256>>>(out + n_logits);
}